// round 3
// baseline (speedup 1.0000x reference)
#include <cuda_runtime.h>
#include <mma.h>
#include <cstdint>
#include <cstddef>

using namespace nvcuda;

// ============================================================================
// Fused LSTM cell, sm_103 (non-'a' PTX target -> no tcgen05; use mma.sync TF32)
//   gates = [prev_h | input](16384x1024) @ W^T(1024x2048) + b ; LSTM epilogue.
// CTA tile: 128 M x 128 N (= 4 gates x 32 h-cols) -> epilogue fused in-CTA.
// 8 warps, warp tile 32x64 (wmma m16n16k8 tf32). 3-stage cp.async pipeline.
// ============================================================================

#define BATCH 16384
#define HID   512
#define KDIM  1024
#define BM    128
#define BK    32
#define LDA   36                      // padded row stride (floats)
#define STAGE_F     (BM * LDA)        // floats per A (or B) tile = 4608
#define STAGE_FLTS  (2 * STAGE_F)     // A+B per stage
#define NST   3
#define LDC   132
#define DYN_BYTES (NST * STAGE_FLTS * 4)   // 110592

__device__ __forceinline__ uint32_t s2u(const void* p) {
    uint32_t a;
    asm("{ .reg .u64 t; cvta.to.shared.u64 t, %1; cvt.u32.u64 %0, t; }"
        : "=r"(a) : "l"(p));
    return a;
}
__device__ __forceinline__ void cp16(uint32_t dst, const float* src) {
    asm volatile("cp.async.cg.shared.global [%0], [%1], 16;"
                 :: "r"(dst), "l"(src));
}
__device__ __forceinline__ float sigmoid_f(float x) {
    return 1.0f / (1.0f + __expf(-x));
}
__device__ __forceinline__ float tanh_f(float x) {
    float e = __expf(2.0f * x);
    return 1.0f - 2.0f / (e + 1.0f);
}

__global__ void __launch_bounds__(256, 1)
lstm_wmma_kernel(const float* __restrict__ input_,
                 const float* __restrict__ prev_h,
                 const float* __restrict__ prev_c,
                 const float* __restrict__ Wi, const float* __restrict__ Wf,
                 const float* __restrict__ Wo, const float* __restrict__ Wg,
                 const float* __restrict__ bi, const float* __restrict__ bf,
                 const float* __restrict__ bo, const float* __restrict__ bg,
                 float* __restrict__ h_out, float* __restrict__ c_out)
{
    extern __shared__ float sm[];
    const uint32_t sbase = s2u(sm);

    const int tid = threadIdx.x;
    const int wid = tid >> 5;
    const int lid = tid & 31;
    const int mb  = blockIdx.y;        // 128 m-tiles
    const int hb  = blockIdx.x;        // 16 h-tiles

    // cp.async per-thread coordinates: 8 chunks of 16B per row of 32 floats
    const int cchunk = tid & 7;        // which 16B chunk in the 128B row
    const int rbase  = tid >> 3;       // 0..31
    const float* wptr[4] = {Wi, Wf, Wo, Wg};   // gate row-blocks 0..3

    const int wm = wid >> 1;           // warp m index 0..3 (32 rows each)
    const int wn = wid & 1;            // warp n index 0..1 (64 cols each)

    wmma::fragment<wmma::accumulator, 16, 16, 8, float> acc[2][4];
    #pragma unroll
    for (int mi = 0; mi < 2; ++mi)
        #pragma unroll
        for (int ni = 0; ni < 4; ++ni)
            wmma::fill_fragment(acc[mi][ni], 0.0f);

    auto issue_stage = [&](int it, int s) {
        const uint32_t sA = sbase + (uint32_t)s * STAGE_FLTS * 4;
        const uint32_t sB = sA + STAGE_F * 4;
        // A = [prev_h | input_] along K; 32-col stage stays inside one source
        const float* asrc = (it < 16) ? prev_h : input_;
        const int kcolA = (it & 15) * BK + cchunk * 4;
        #pragma unroll
        for (int i = 0; i < 4; ++i) {
            const int r = rbase + 32 * i;
            cp16(sA + (uint32_t)(r * LDA + cchunk * 4) * 4,
                 asrc + (size_t)(mb * 128 + r) * HID + kcolA);
        }
        const int kcolW = it * BK + cchunk * 4;
        #pragma unroll
        for (int i = 0; i < 4; ++i) {       // gate i occupies smem rows [32i,32i+32)
            const int r = rbase + 32 * i;
            cp16(sB + (uint32_t)(r * LDA + cchunk * 4) * 4,
                 wptr[i] + (size_t)(hb * 32 + rbase) * KDIM + kcolW);
        }
        asm volatile("cp.async.commit_group;" ::: "memory");
    };

    // prologue: stages for it = 0, 1
    issue_stage(0, 0);
    issue_stage(1, 1);

    const int NITER = KDIM / BK;       // 32
    for (int it = 0; it < NITER; ++it) {
        if (it < NITER - 1) asm volatile("cp.async.wait_group 1;" ::: "memory");
        else                asm volatile("cp.async.wait_group 0;" ::: "memory");
        __syncthreads();

        if (it + 2 < NITER) issue_stage(it + 2, (it + 2) % NST);

        const float* tA = sm + (it % NST) * STAGE_FLTS;
        const float* tB = tA + STAGE_F;

        #pragma unroll
        for (int ks = 0; ks < 4; ++ks) {
            wmma::fragment<wmma::matrix_a, 16, 16, 8, wmma::precision::tf32,
                           wmma::row_major> af[2];
            wmma::fragment<wmma::matrix_b, 16, 16, 8, wmma::precision::tf32,
                           wmma::col_major> bfr[4];
            #pragma unroll
            for (int mi = 0; mi < 2; ++mi) {
                wmma::load_matrix_sync(af[mi],
                    tA + (wm * 32 + mi * 16) * LDA + ks * 8, LDA);
                #pragma unroll
                for (int e = 0; e < af[mi].num_elements; ++e)
                    af[mi].x[e] = wmma::__float_to_tf32(af[mi].x[e]);
            }
            #pragma unroll
            for (int ni = 0; ni < 4; ++ni) {
                wmma::load_matrix_sync(bfr[ni],
                    tB + (wn * 64 + ni * 16) * LDA + ks * 8, LDA);
                #pragma unroll
                for (int e = 0; e < bfr[ni].num_elements; ++e)
                    bfr[ni].x[e] = wmma::__float_to_tf32(bfr[ni].x[e]);
            }
            #pragma unroll
            for (int mi = 0; mi < 2; ++mi)
                #pragma unroll
                for (int ni = 0; ni < 4; ++ni)
                    wmma::mma_sync(acc[mi][ni], af[mi], bfr[ni], acc[mi][ni]);
        }
    }

    // ---------------- epilogue: dump acc -> smem, fuse LSTM ------------------
    __syncthreads();                    // all cp.async drained; smem reusable
    float* sC = sm;                     // 128 x LDC
    #pragma unroll
    for (int mi = 0; mi < 2; ++mi)
        #pragma unroll
        for (int ni = 0; ni < 4; ++ni)
            wmma::store_matrix_sync(
                sC + (wm * 32 + mi * 16) * LDC + wn * 64 + ni * 16,
                acc[mi][ni], LDC, wmma::mem_row_major);
    __syncthreads();

    // warp w handles rows [16w, 16w+16); lane l handles h-col l (stride-1, no
    // bank conflicts, coalesced gmem)
    const int hg = hb * 32 + lid;
    const float vbi = __ldg(&bi[hg]);
    const float vbf = __ldg(&bf[hg]);
    const float vbo = __ldg(&bo[hg]);
    const float vbg = __ldg(&bg[hg]);

    #pragma unroll
    for (int rr = 0; rr < 16; ++rr) {
        const int r = wid * 16 + rr;
        const size_t off = (size_t)(mb * 128 + r) * HID + hg;
        const float* row = sC + r * LDC;
        const float gi = sigmoid_f(row[lid]        + vbi);
        const float gf = sigmoid_f(row[32 + lid]   + vbf);
        const float go = sigmoid_f(row[64 + lid]   + vbo);
        const float gg = tanh_f   (row[96 + lid]   + vbg);
        const float pc = __ldg(&prev_c[off]);
        const float c  = gf * pc + gi * gg;
        h_out[off] = tanh_f(c) * go;
        c_out[off] = c;
    }
}

// ---------------------------------------------------------------------------
extern "C" void kernel_launch(void* const* d_in, const int* in_sizes, int n_in,
                              void* d_out, int out_size) {
    const float* input_ = (const float*)d_in[0];
    const float* prev_h = (const float*)d_in[1];
    const float* prev_c = (const float*)d_in[2];
    const float* W_i = (const float*)d_in[3];  const float* b_i = (const float*)d_in[4];
    const float* W_f = (const float*)d_in[5];  const float* b_f = (const float*)d_in[6];
    const float* W_g = (const float*)d_in[7];  const float* b_g = (const float*)d_in[8];
    const float* W_o = (const float*)d_in[9];  const float* b_o = (const float*)d_in[10];

    float* h_out = (float*)d_out;
    float* c_out = h_out + (size_t)BATCH * HID;

    cudaFuncSetAttribute(lstm_wmma_kernel,
                         cudaFuncAttributeMaxDynamicSharedMemorySize, DYN_BYTES);

    dim3 grid(16, 128);                // h-tiles fastest -> W resident in L2
    lstm_wmma_kernel<<<grid, 256, DYN_BYTES>>>(
        input_, prev_h, prev_c,
        W_i, W_f, W_o, W_g,
        b_i, b_f, b_o, b_g,
        h_out, c_out);
}

// round 5
// speedup vs baseline: 3.9726x; 3.9726x over previous
#include <cuda_runtime.h>
#include <cuda_fp16.h>
#include <cstdint>
#include <cstddef>

// ============================================================================
// Fused LSTM cell, sm_103 (plain PTX target): fp16 mma.m16n8k16 + ldmatrix.
//  Pre-pass: fp32 -> fp16 scratch (A = [prev_h|input], W gathered per h-tile).
//  GEMM: CTA 128M x 128N (4 gates x 32 h), 8 warps (warp 32x64), BK=32,
//        4-stage cp.async, swizzled smem. Fused sigmoid/tanh epilogue.
//  R5 fix: B ldmatrix must be NON-trans (W is [n][k], k contiguous, which
//  already matches the mma .col B fragment: lane=n*4+k/2, halves=consec k).
// ============================================================================

#define BATCH 16384
#define HID   512
#define KD    1024
#define BM    128
#define BN    128
#define BK    32
#define NST   4
#define NITER (KD / BK)            // 32
#define LDC   132
#define STAGE_BYTES 16384          // A 128x32 fp16 (8KB) + B 128x32 fp16 (8KB)
#define DYN_BYTES   67584          // max(4*16384, 128*132*4)

__device__ __align__(256) __half g_A16[(size_t)BATCH * KD];     // 32 MB
__device__ __align__(256) __half g_W16[(size_t)2048  * KD];     // 4 MB

// ---------------------------------------------------------------------------
__device__ __forceinline__ uint32_t s2u(const void* p) {
    uint32_t a;
    asm("{ .reg .u64 t; cvta.to.shared.u64 t, %1; cvt.u32.u64 %0, t; }"
        : "=r"(a) : "l"(p));
    return a;
}
__device__ __forceinline__ void cp16(uint32_t dst, const void* src) {
    asm volatile("cp.async.cg.shared.global [%0], [%1], 16;"
                 :: "r"(dst), "l"(src));
}
__device__ __forceinline__ void ldm_x4(uint32_t* d, uint32_t a) {
    asm volatile("ldmatrix.sync.aligned.m8n8.x4.shared.b16 {%0,%1,%2,%3}, [%4];"
                 : "=r"(d[0]), "=r"(d[1]), "=r"(d[2]), "=r"(d[3]) : "r"(a));
}
__device__ __forceinline__ void mma16816(float* d, const uint32_t* a,
                                         const uint32_t* b) {
    asm volatile(
        "mma.sync.aligned.m16n8k16.row.col.f32.f16.f16.f32 "
        "{%0,%1,%2,%3}, {%4,%5,%6,%7}, {%8,%9}, {%0,%1,%2,%3};"
        : "+f"(d[0]), "+f"(d[1]), "+f"(d[2]), "+f"(d[3])
        : "r"(a[0]), "r"(a[1]), "r"(a[2]), "r"(a[3]), "r"(b[0]), "r"(b[1]));
}
__device__ __forceinline__ float sigmoid_f(float x) {
    return 1.0f / (1.0f + __expf(-x));
}
__device__ __forceinline__ float tanh_f(float x) {
    float e = __expf(2.0f * x);
    return 1.0f - 2.0f / (e + 1.0f);
}
// smem byte offset for (row, 16B-chunk) with xor swizzle (64B rows, 4 chunks)
__device__ __forceinline__ uint32_t sw(int r, int c) {
    return (uint32_t)(r * 64 + ((c ^ ((r >> 1) & 3)) << 4));
}

// ---------------------------------------------------------------------------
// pre-pass: A16[m][k] = (k<512 ? prev_h[m][k] : input_[m][k-512]), rn-rounded
__global__ void __launch_bounds__(256) convA(const float* __restrict__ ph,
                                             const float* __restrict__ xin) {
    const size_t i = (size_t)blockIdx.x * 256 + threadIdx.x;   // 4 floats each
    const int row = (int)(i >> 8);
    const int col = (int)(i & 255) * 4;
    const float* s = (col < 512) ? (ph + (size_t)row * 512 + col)
                                 : (xin + (size_t)row * 512 + (col - 512));
    const float4 v = *(const float4*)s;
    __half2 h0 = __floats2half2_rn(v.x, v.y);
    __half2 h1 = __floats2half2_rn(v.z, v.w);
    uint2 u;
    u.x = *reinterpret_cast<uint32_t*>(&h0);
    u.y = *reinterpret_cast<uint32_t*>(&h1);
    *(uint2*)(g_A16 + i * 4) = u;
}
// pre-pass: W16 row (ht*128 + r) = W_{gate r/32}[ht*32 + r%32][:], gates i,f,o,g
__global__ void __launch_bounds__(256) convW(const float* __restrict__ Wi,
                                             const float* __restrict__ Wf,
                                             const float* __restrict__ Wo,
                                             const float* __restrict__ Wg) {
    const size_t i = (size_t)blockIdx.x * 256 + threadIdx.x;   // 4 floats each
    const int orow = (int)(i >> 8);
    const int col  = (int)(i & 255) * 4;
    const int ht = orow >> 7, r = orow & 127;
    const int gate = r >> 5, hrow = ht * 32 + (r & 31);
    const float* W = (gate == 0) ? Wi : (gate == 1) ? Wf : (gate == 2) ? Wo : Wg;
    const float4 v = *(const float4*)(W + (size_t)hrow * KD + col);
    __half2 h0 = __floats2half2_rn(v.x, v.y);
    __half2 h1 = __floats2half2_rn(v.z, v.w);
    uint2 u;
    u.x = *reinterpret_cast<uint32_t*>(&h0);
    u.y = *reinterpret_cast<uint32_t*>(&h1);
    *(uint2*)(g_W16 + i * 4) = u;
}

// ---------------------------------------------------------------------------
__global__ void __launch_bounds__(256, 2)
lstm_fp16_gemm(const float* __restrict__ prev_c,
               const float* __restrict__ bi, const float* __restrict__ bf,
               const float* __restrict__ bo, const float* __restrict__ bg,
               float* __restrict__ h_out, float* __restrict__ c_out)
{
    extern __shared__ char smc[];
    const uint32_t sb = s2u(smc);

    const int tid = threadIdx.x;
    const int wid = tid >> 5;
    const int lid = tid & 31;
    const int hb  = blockIdx.x;            // 16 h-tiles (fastest: W hot in L2)
    const int mb  = blockIdx.y;            // 128 m-tiles
    const int wm  = wid >> 1;              // 0..3
    const int wn  = wid & 1;               // 0..1

    // ---- cp.async thread mapping: row = tid/2, two 16B chunks each ----------
    const int cr = tid >> 1;
    const int cb = (tid & 1) * 2;
    const __half* gA = g_A16 + (size_t)(mb * 128 + cr) * KD + cb * 8;
    const __half* gB = g_W16 + (size_t)(hb * 128 + cr) * KD + cb * 8;
    const uint32_t dA0 = sb + sw(cr, cb),     dA1 = sb + sw(cr, cb + 1);
    const uint32_t dB0 = dA0 + 8192,          dB1 = dA1 + 8192;

    auto issue = [&](int kt) {
        const uint32_t so = (uint32_t)(kt & 3) * STAGE_BYTES;
        const __half* a = gA + kt * BK;
        const __half* b = gB + kt * BK;
        cp16(dA0 + so, a);
        cp16(dA1 + so, a + 8);
        cp16(dB0 + so, b);
        cp16(dB1 + so, b + 8);
        asm volatile("cp.async.commit_group;" ::: "memory");
    };

    issue(0); issue(1); issue(2);

    float acc[2][8][4];
    #pragma unroll
    for (int mi = 0; mi < 2; ++mi)
        #pragma unroll
        for (int ni = 0; ni < 8; ++ni)
            #pragma unroll
            for (int q = 0; q < 4; ++q) acc[mi][ni][q] = 0.0f;

    // ldmatrix lane coordinates (identical mapping for A and B: both are
    // row-major [outer][k] tiles; non-trans ldmatrix matches both fragments)
    const int a_r = (lid & 15);            // row within 16
    const int a_c = (lid >> 4);            // k-chunk lo/hi
    const int b_r = ((lid >> 4) << 3) + (lid & 7);   // n row within 16
    const int b_c = ((lid >> 3) & 1);                // k-chunk lo/hi

    #pragma unroll 1
    for (int it = 0; it < NITER; ++it) {
        if (it + 2 < NITER)      asm volatile("cp.async.wait_group 2;" ::: "memory");
        else if (it + 1 < NITER) asm volatile("cp.async.wait_group 1;" ::: "memory");
        else                     asm volatile("cp.async.wait_group 0;" ::: "memory");
        __syncthreads();

        if (it + 3 < NITER) issue(it + 3);

        const uint32_t smA = sb + (uint32_t)(it & 3) * STAGE_BYTES;
        const uint32_t smB = smA + 8192;

        #pragma unroll
        for (int ks = 0; ks < 2; ++ks) {
            uint32_t a[2][4], b[8][2];
            #pragma unroll
            for (int mi = 0; mi < 2; ++mi) {
                const int r = wm * 32 + mi * 16 + a_r;
                ldm_x4(a[mi], smA + sw(r, ks * 2 + a_c));
            }
            #pragma unroll
            for (int n2 = 0; n2 < 4; ++n2) {
                uint32_t t4[4];
                const int r = wn * 64 + n2 * 16 + b_r;
                ldm_x4(t4, smB + sw(r, ks * 2 + b_c));   // NON-trans (fix)
                b[n2 * 2][0] = t4[0]; b[n2 * 2][1] = t4[1];
                b[n2 * 2 + 1][0] = t4[2]; b[n2 * 2 + 1][1] = t4[3];
            }
            #pragma unroll
            for (int mi = 0; mi < 2; ++mi)
                #pragma unroll
                for (int ni = 0; ni < 8; ++ni)
                    mma16816(acc[mi][ni], a[mi], b[ni]);
        }
    }

    // ---- epilogue: acc -> smem, fused LSTM ----------------------------------
    __syncthreads();
    float* sC = (float*)smc;
    #pragma unroll
    for (int mi = 0; mi < 2; ++mi)
        #pragma unroll
        for (int ni = 0; ni < 8; ++ni) {
            const int m = wm * 32 + mi * 16 + (lid >> 2);
            const int n = wn * 64 + ni * 8 + (lid & 3) * 2;
            *(float2*)(sC + m * LDC + n) =
                make_float2(acc[mi][ni][0], acc[mi][ni][1]);
            *(float2*)(sC + (m + 8) * LDC + n) =
                make_float2(acc[mi][ni][2], acc[mi][ni][3]);
        }
    __syncthreads();

    const int hg = hb * 32 + lid;
    const float vbi = __ldg(&bi[hg]);
    const float vbf = __ldg(&bf[hg]);
    const float vbo = __ldg(&bo[hg]);
    const float vbg = __ldg(&bg[hg]);

    #pragma unroll
    for (int rr = 0; rr < 16; ++rr) {
        const int r = wid * 16 + rr;
        const size_t off = (size_t)(mb * 128 + r) * HID + hg;
        const float* row = sC + r * LDC;
        const float gi = sigmoid_f(row[lid]      + vbi);
        const float gf = sigmoid_f(row[32 + lid] + vbf);
        const float go = sigmoid_f(row[64 + lid] + vbo);
        const float gg = tanh_f   (row[96 + lid] + vbg);
        const float pc = __ldg(&prev_c[off]);
        const float c  = gf * pc + gi * gg;
        h_out[off] = tanh_f(c) * go;
        c_out[off] = c;
    }
}

// ---------------------------------------------------------------------------
extern "C" void kernel_launch(void* const* d_in, const int* in_sizes, int n_in,
                              void* d_out, int out_size) {
    const float* input_ = (const float*)d_in[0];
    const float* prev_h = (const float*)d_in[1];
    const float* prev_c = (const float*)d_in[2];
    const float* W_i = (const float*)d_in[3];  const float* b_i = (const float*)d_in[4];
    const float* W_f = (const float*)d_in[5];  const float* b_f = (const float*)d_in[6];
    const float* W_g = (const float*)d_in[7];  const float* b_g = (const float*)d_in[8];
    const float* W_o = (const float*)d_in[9];  const float* b_o = (const float*)d_in[10];

    float* h_out = (float*)d_out;
    float* c_out = h_out + (size_t)BATCH * HID;

    convA<<<(BATCH * KD / 4) / 256, 256>>>(prev_h, input_);
    convW<<<(2048 * KD / 4) / 256, 256>>>(W_i, W_f, W_o, W_g);

    cudaFuncSetAttribute(lstm_fp16_gemm,
                         cudaFuncAttributeMaxDynamicSharedMemorySize, DYN_BYTES);
    dim3 grid(16, 128);
    lstm_fp16_gemm<<<grid, 256, DYN_BYTES>>>(prev_c, b_i, b_f, b_o, b_g,
                                             h_out, c_out);
}

// round 7
// speedup vs baseline: 4.9782x; 1.2531x over previous
#include <cuda_runtime.h>
#include <cuda_fp16.h>
#include <cstdint>
#include <cstddef>

// ============================================================================
// Fused LSTM cell, sm_103: fp16 mma.m16n8k16 + ldmatrix.
//  R7: fix pre-pass coverage (R6 converted only 25% of scratch). GEMM: BK=64,
//  NST=3 (96KB smem, 2 CTA/SM), software-pipelined fragment loads.
// ============================================================================

#define BATCH 16384
#define HID   512
#define KD    1024
#define BK    64
#define NST   3
#define NITER (KD / BK)            // 16
#define LDC   132
#define STAGE_BYTES 32768          // A 128x64 fp16 (16KB) + B (16KB)
#define DYN_BYTES   98304

__device__ __align__(256) __half g_A16[(size_t)BATCH * KD];     // 32 MB
__device__ __align__(256) __half g_W16[(size_t)2048  * KD];     // 4 MB

// ---------------------------------------------------------------------------
__device__ __forceinline__ uint32_t s2u(const void* p) {
    uint32_t a;
    asm("{ .reg .u64 t; cvta.to.shared.u64 t, %1; cvt.u32.u64 %0, t; }"
        : "=r"(a) : "l"(p));
    return a;
}
__device__ __forceinline__ void cp16(uint32_t dst, const void* src) {
    asm volatile("cp.async.cg.shared.global [%0], [%1], 16;"
                 :: "r"(dst), "l"(src));
}
__device__ __forceinline__ void ldm_x4(uint32_t* d, uint32_t a) {
    asm volatile("ldmatrix.sync.aligned.m8n8.x4.shared.b16 {%0,%1,%2,%3}, [%4];"
                 : "=r"(d[0]), "=r"(d[1]), "=r"(d[2]), "=r"(d[3]) : "r"(a));
}
__device__ __forceinline__ void mma16816(float* d, const uint32_t* a,
                                         const uint32_t* b) {
    asm volatile(
        "mma.sync.aligned.m16n8k16.row.col.f32.f16.f16.f32 "
        "{%0,%1,%2,%3}, {%4,%5,%6,%7}, {%8,%9}, {%0,%1,%2,%3};"
        : "+f"(d[0]), "+f"(d[1]), "+f"(d[2]), "+f"(d[3])
        : "r"(a[0]), "r"(a[1]), "r"(a[2]), "r"(a[3]), "r"(b[0]), "r"(b[1]));
}
__device__ __forceinline__ float sigmoid_f(float x) {
    return 1.0f / (1.0f + __expf(-x));
}
__device__ __forceinline__ float tanh_f(float x) {
    float e = __expf(2.0f * x);
    return 1.0f - 2.0f / (e + 1.0f);
}
// smem byte offset for (row, 16B-chunk), rows are 128B (8 chunks), xor swizzle
__device__ __forceinline__ uint32_t sw(int r, int c) {
    return (uint32_t)(r * 128 + ((c ^ (r & 7)) << 4));
}

// ---------------------------------------------------------------------------
// pre-pass: A16[m][k] = (k<512 ? prev_h : input_), grid-stride, 4 groups/thr
__global__ void __launch_bounds__(256) convA(const float* __restrict__ ph,
                                             const float* __restrict__ xin) {
    const size_t idx = (size_t)blockIdx.x * 256 + threadIdx.x;  // 1M threads
    #pragma unroll
    for (int j = 0; j < 4; ++j) {
        const size_t i = idx + (size_t)j * 1048576;             // 4M groups
        const int row = (int)(i >> 8);
        const int col = (int)(i & 255) * 4;
        const float* s = (col < 512) ? (ph + (size_t)row * 512 + col)
                                     : (xin + (size_t)row * 512 + (col - 512));
        const float4 v = *(const float4*)s;
        __half2 h0 = __floats2half2_rn(v.x, v.y);
        __half2 h1 = __floats2half2_rn(v.z, v.w);
        uint2 u;
        u.x = *reinterpret_cast<uint32_t*>(&h0);
        u.y = *reinterpret_cast<uint32_t*>(&h1);
        *(uint2*)(g_A16 + i * 4) = u;
    }
}
// pre-pass: W16 row (ht*128 + r) = W_{gate r/32}[ht*32 + r%32][:]
__global__ void __launch_bounds__(256) convW(const float* __restrict__ Wi,
                                             const float* __restrict__ Wf,
                                             const float* __restrict__ Wo,
                                             const float* __restrict__ Wg) {
    const size_t idx = (size_t)blockIdx.x * 256 + threadIdx.x;  // 128K threads
    #pragma unroll
    for (int j = 0; j < 4; ++j) {
        const size_t i = idx + (size_t)j * 131072;              // 512K groups
        const int orow = (int)(i >> 8);
        const int col  = (int)(i & 255) * 4;
        const int ht = orow >> 7, r = orow & 127;
        const int gate = r >> 5, hrow = ht * 32 + (r & 31);
        const float* W = (gate == 0) ? Wi : (gate == 1) ? Wf
                       : (gate == 2) ? Wo : Wg;
        const float4 v = *(const float4*)(W + (size_t)hrow * KD + col);
        __half2 h0 = __floats2half2_rn(v.x, v.y);
        __half2 h1 = __floats2half2_rn(v.z, v.w);
        uint2 u;
        u.x = *reinterpret_cast<uint32_t*>(&h0);
        u.y = *reinterpret_cast<uint32_t*>(&h1);
        *(uint2*)(g_W16 + i * 4) = u;
    }
}

// ---------------------------------------------------------------------------
__global__ void __launch_bounds__(256, 2)
lstm_fp16_gemm(const float* __restrict__ prev_c,
               const float* __restrict__ bi, const float* __restrict__ bf,
               const float* __restrict__ bo, const float* __restrict__ bg,
               float* __restrict__ h_out, float* __restrict__ c_out)
{
    extern __shared__ char smc[];
    const uint32_t sb = s2u(smc);

    const int tid = threadIdx.x;
    const int wid = tid >> 5;
    const int lid = tid & 31;
    const int hb  = blockIdx.x;            // 16 h-tiles (fastest: W hot in L2)
    const int mb  = blockIdx.y;            // 128 m-tiles
    const int wm  = wid >> 1;              // 0..3
    const int wn  = wid & 1;               // 0..1

    // ---- cp.async mapping: 8 threads cover one 128B row ---------------------
    const int cr = tid >> 3;               // 0..31
    const int cc = tid & 7;                // chunk 0..7
    const __half* gA = g_A16 + (size_t)(mb * 128) * KD + cc * 8;
    const __half* gB = g_W16 + (size_t)(hb * 128) * KD + cc * 8;

    auto issue = [&](int kt) {
        const uint32_t so = sb + (uint32_t)(kt % NST) * STAGE_BYTES;
        const int kcol = kt * BK;
        #pragma unroll
        for (int i = 0; i < 4; ++i) {
            const int r = cr + 32 * i;
            cp16(so + sw(r, cc),         gA + (size_t)r * KD + kcol);
            cp16(so + 16384 + sw(r, cc), gB + (size_t)r * KD + kcol);
        }
        asm volatile("cp.async.commit_group;" ::: "memory");
    };

    issue(0); issue(1);

    float acc[2][8][4];
    #pragma unroll
    for (int mi = 0; mi < 2; ++mi)
        #pragma unroll
        for (int ni = 0; ni < 8; ++ni)
            #pragma unroll
            for (int q = 0; q < 4; ++q) acc[mi][ni][q] = 0.0f;

    // ldmatrix lane coordinates
    const int a_r = (lid & 15);
    const int a_c = (lid >> 4);
    const int b_r = ((lid >> 4) << 3) + (lid & 7);
    const int b_c = ((lid >> 3) & 1);

    #pragma unroll 1
    for (int it = 0; it < NITER; ++it) {
        if (it + 1 < NITER) asm volatile("cp.async.wait_group 1;" ::: "memory");
        else                asm volatile("cp.async.wait_group 0;" ::: "memory");
        __syncthreads();

        if (it + 2 < NITER) issue(it + 2);

        const uint32_t smA = sb + (uint32_t)(it % NST) * STAGE_BYTES;
        const uint32_t smB = smA + 16384;

        uint32_t a[2][2][4], b[2][8][2];   // double-buffered fragments
        // preload ks = 0
        {
            #pragma unroll
            for (int mi = 0; mi < 2; ++mi)
                ldm_x4(a[0][mi], smA + sw(wm * 32 + mi * 16 + a_r, a_c));
            #pragma unroll
            for (int n2 = 0; n2 < 4; ++n2) {
                uint32_t t4[4];
                ldm_x4(t4, smB + sw(wn * 64 + n2 * 16 + b_r, b_c));
                b[0][n2 * 2][0] = t4[0]; b[0][n2 * 2][1] = t4[1];
                b[0][n2 * 2 + 1][0] = t4[2]; b[0][n2 * 2 + 1][1] = t4[3];
            }
        }
        #pragma unroll
        for (int ks = 0; ks < 4; ++ks) {
            const int cur = ks & 1, nxt = cur ^ 1;
            if (ks < 3) {                  // preload ks+1 while mma'ing ks
                const int kc = (ks + 1) * 2;
                #pragma unroll
                for (int mi = 0; mi < 2; ++mi)
                    ldm_x4(a[nxt][mi], smA + sw(wm * 32 + mi * 16 + a_r, kc + a_c));
                #pragma unroll
                for (int n2 = 0; n2 < 4; ++n2) {
                    uint32_t t4[4];
                    ldm_x4(t4, smB + sw(wn * 64 + n2 * 16 + b_r, kc + b_c));
                    b[nxt][n2 * 2][0] = t4[0]; b[nxt][n2 * 2][1] = t4[1];
                    b[nxt][n2 * 2 + 1][0] = t4[2]; b[nxt][n2 * 2 + 1][1] = t4[3];
                }
            }
            #pragma unroll
            for (int mi = 0; mi < 2; ++mi)
                #pragma unroll
                for (int ni = 0; ni < 8; ++ni)
                    mma16816(acc[mi][ni], a[cur][mi], b[cur][ni]);
        }
    }

    // ---- epilogue: acc -> smem, fused LSTM ----------------------------------
    __syncthreads();
    float* sC = (float*)smc;
    #pragma unroll
    for (int mi = 0; mi < 2; ++mi)
        #pragma unroll
        for (int ni = 0; ni < 8; ++ni) {
            const int m = wm * 32 + mi * 16 + (lid >> 2);
            const int n = wn * 64 + ni * 8 + (lid & 3) * 2;
            *(float2*)(sC + m * LDC + n) =
                make_float2(acc[mi][ni][0], acc[mi][ni][1]);
            *(float2*)(sC + (m + 8) * LDC + n) =
                make_float2(acc[mi][ni][2], acc[mi][ni][3]);
        }
    __syncthreads();

    const int hg = hb * 32 + lid;
    const float vbi = __ldg(&bi[hg]);
    const float vbf = __ldg(&bf[hg]);
    const float vbo = __ldg(&bo[hg]);
    const float vbg = __ldg(&bg[hg]);

    #pragma unroll
    for (int rr = 0; rr < 16; ++rr) {
        const int r = wid * 16 + rr;
        const size_t off = (size_t)(mb * 128 + r) * HID + hg;
        const float* row = sC + r * LDC;
        const float gi = sigmoid_f(row[lid]      + vbi);
        const float gf = sigmoid_f(row[32 + lid] + vbf);
        const float go = sigmoid_f(row[64 + lid] + vbo);
        const float gg = tanh_f   (row[96 + lid] + vbg);
        const float pc = __ldg(&prev_c[off]);
        const float c  = gf * pc + gi * gg;
        h_out[off] = tanh_f(c) * go;
        c_out[off] = c;
    }
}

// ---------------------------------------------------------------------------
extern "C" void kernel_launch(void* const* d_in, const int* in_sizes, int n_in,
                              void* d_out, int out_size) {
    const float* input_ = (const float*)d_in[0];
    const float* prev_h = (const float*)d_in[1];
    const float* prev_c = (const float*)d_in[2];
    const float* W_i = (const float*)d_in[3];  const float* b_i = (const float*)d_in[4];
    const float* W_f = (const float*)d_in[5];  const float* b_f = (const float*)d_in[6];
    const float* W_g = (const float*)d_in[7];  const float* b_g = (const float*)d_in[8];
    const float* W_o = (const float*)d_in[9];  const float* b_o = (const float*)d_in[10];

    float* h_out = (float*)d_out;
    float* c_out = h_out + (size_t)BATCH * HID;

    convA<<<4096, 256>>>(prev_h, input_);          // 1M thr x 4 = 4M groups
    convW<<<512, 256>>>(W_i, W_f, W_o, W_g);       // 128K thr x 4 = 512K groups

    cudaFuncSetAttribute(lstm_fp16_gemm,
                         cudaFuncAttributeMaxDynamicSharedMemorySize, DYN_BYTES);
    dim3 grid(16, 128);
    lstm_fp16_gemm<<<grid, 256, DYN_BYTES>>>(prev_c, b_i, b_f, b_o, b_g,
                                             h_out, c_out);
}

// round 8
// speedup vs baseline: 6.0995x; 1.2252x over previous
#include <cuda_runtime.h>
#include <cuda_fp16.h>
#include <cstdint>
#include <cstddef>

// ============================================================================
// Fused LSTM cell, sm_103: fp16 mma.m16n8k16 + ldmatrix.
//  R8: merged pre-pass, gate-interleaved W16 layout -> register-local epilogue
//  (no smem C round-trip), biases folded into accumulator init.
//  W16 row r in h-tile: gate = bits[3:4] of r (i,f,o,g), h = {bit6}*16 +
//  {bit5}*8 + bits[0:2]. Thread fragment ni: gate = ni&3, h_octet = ni>>2.
// ============================================================================

#define BATCH 16384
#define HID   512
#define KD    1024
#define BK    64
#define NST   3
#define NITER (KD / BK)            // 16
#define STAGE_BYTES 32768          // A 128x64 fp16 (16KB) + B (16KB)
#define DYN_BYTES   98304

__device__ __align__(256) __half g_A16[(size_t)BATCH * KD];     // 32 MB
__device__ __align__(256) __half g_W16[(size_t)2048  * KD];     // 4 MB

// ---------------------------------------------------------------------------
__device__ __forceinline__ uint32_t s2u(const void* p) {
    uint32_t a;
    asm("{ .reg .u64 t; cvta.to.shared.u64 t, %1; cvt.u32.u64 %0, t; }"
        : "=r"(a) : "l"(p));
    return a;
}
__device__ __forceinline__ void cp16(uint32_t dst, const void* src) {
    asm volatile("cp.async.cg.shared.global [%0], [%1], 16;"
                 :: "r"(dst), "l"(src));
}
__device__ __forceinline__ void ldm_x4(uint32_t* d, uint32_t a) {
    asm volatile("ldmatrix.sync.aligned.m8n8.x4.shared.b16 {%0,%1,%2,%3}, [%4];"
                 : "=r"(d[0]), "=r"(d[1]), "=r"(d[2]), "=r"(d[3]) : "r"(a));
}
__device__ __forceinline__ void mma16816(float* d, const uint32_t* a,
                                         const uint32_t* b) {
    asm volatile(
        "mma.sync.aligned.m16n8k16.row.col.f32.f16.f16.f32 "
        "{%0,%1,%2,%3}, {%4,%5,%6,%7}, {%8,%9}, {%0,%1,%2,%3};"
        : "+f"(d[0]), "+f"(d[1]), "+f"(d[2]), "+f"(d[3])
        : "r"(a[0]), "r"(a[1]), "r"(a[2]), "r"(a[3]), "r"(b[0]), "r"(b[1]));
}
__device__ __forceinline__ float sigmoid_f(float x) {
    return 1.0f / (1.0f + __expf(-x));
}
__device__ __forceinline__ float tanh_f(float x) {
    float e = __expf(2.0f * x);
    return 1.0f - 2.0f / (e + 1.0f);
}
// smem byte offset for (row, 16B-chunk), rows are 128B (8 chunks), xor swizzle
__device__ __forceinline__ uint32_t sw(int r, int c) {
    return (uint32_t)(r * 128 + ((c ^ (r & 7)) << 4));
}

// ---------------------------------------------------------------------------
// merged pre-pass: blocks [0,4096) convert A, blocks [4096,4608) convert W.
__global__ void __launch_bounds__(256) convAW(const float* __restrict__ ph,
                                              const float* __restrict__ xin,
                                              const float* __restrict__ Wi,
                                              const float* __restrict__ Wf,
                                              const float* __restrict__ Wo,
                                              const float* __restrict__ Wg) {
    if (blockIdx.x < 4096) {
        const size_t idx = (size_t)blockIdx.x * 256 + threadIdx.x;  // 1M thr
        #pragma unroll
        for (int j = 0; j < 4; ++j) {
            const size_t i = idx + (size_t)j * 1048576;             // 4M groups
            const int row = (int)(i >> 8);
            const int col = (int)(i & 255) * 4;
            const float* s = (col < 512) ? (ph + (size_t)row * 512 + col)
                                         : (xin + (size_t)row * 512 + (col - 512));
            const float4 v = *(const float4*)s;
            __half2 h0 = __floats2half2_rn(v.x, v.y);
            __half2 h1 = __floats2half2_rn(v.z, v.w);
            uint2 u;
            u.x = *reinterpret_cast<uint32_t*>(&h0);
            u.y = *reinterpret_cast<uint32_t*>(&h1);
            *(uint2*)(g_A16 + i * 4) = u;
        }
    } else {
        const size_t idx = (size_t)(blockIdx.x - 4096) * 256 + threadIdx.x;
        #pragma unroll
        for (int j = 0; j < 4; ++j) {
            const size_t i = idx + (size_t)j * 131072;              // 512K groups
            const int orow = (int)(i >> 8);
            const int col  = (int)(i & 255) * 4;
            const int ht = orow >> 7, r = orow & 127;
            // gate-interleaved layout: gate = bits[3:4], h = b6*16 + b5*8 + b[0:2]
            const int gate = (r >> 3) & 3;
            const int h    = ((r >> 6) << 4) + (((r >> 5) & 1) << 3) + (r & 7);
            const int hrow = ht * 32 + h;
            const float* W = (gate == 0) ? Wi : (gate == 1) ? Wf
                           : (gate == 2) ? Wo : Wg;
            const float4 v = *(const float4*)(W + (size_t)hrow * KD + col);
            __half2 h0 = __floats2half2_rn(v.x, v.y);
            __half2 h1 = __floats2half2_rn(v.z, v.w);
            uint2 u;
            u.x = *reinterpret_cast<uint32_t*>(&h0);
            u.y = *reinterpret_cast<uint32_t*>(&h1);
            *(uint2*)(g_W16 + i * 4) = u;
        }
    }
}

// ---------------------------------------------------------------------------
__global__ void __launch_bounds__(256, 2)
lstm_fp16_gemm(const float* __restrict__ prev_c,
               const float* __restrict__ bi, const float* __restrict__ bf,
               const float* __restrict__ bo, const float* __restrict__ bg,
               float* __restrict__ h_out, float* __restrict__ c_out)
{
    extern __shared__ char smc[];
    const uint32_t sb = s2u(smc);

    const int tid = threadIdx.x;
    const int wid = tid >> 5;
    const int lid = tid & 31;
    const int hb  = blockIdx.x;            // 16 h-tiles (fastest: W hot in L2)
    const int mb  = blockIdx.y;            // 128 m-tiles
    const int wm  = wid >> 1;              // 0..3
    const int wn  = wid & 1;               // 0..1

    // ---- cp.async mapping: 8 threads cover one 128B row ---------------------
    const int cr = tid >> 3;               // 0..31
    const int cc = tid & 7;                // chunk 0..7
    const __half* gA = g_A16 + (size_t)(mb * 128) * KD + cc * 8;
    const __half* gB = g_W16 + (size_t)(hb * 128) * KD + cc * 8;

    auto issue = [&](int kt) {
        const uint32_t so = sb + (uint32_t)(kt % NST) * STAGE_BYTES;
        const int kcol = kt * BK;
        #pragma unroll
        for (int i = 0; i < 4; ++i) {
            const int r = cr + 32 * i;
            cp16(so + sw(r, cc),         gA + (size_t)r * KD + kcol);
            cp16(so + 16384 + sw(r, cc), gB + (size_t)r * KD + kcol);
        }
        asm volatile("cp.async.commit_group;" ::: "memory");
    };

    issue(0); issue(1);

    // ---- accumulators pre-loaded with biases (GEMM adds them for free) ------
    // fragment ni: gate = ni&3 (i,f,o,g), h_octet = ni>>2;
    // cols: h = hb*32 + wn*16 + (ni>>2)*8 + (lid&3)*2 + e, rows q: {r, r, r+8, r+8}
    float acc[2][8][4];
    {
        const int hq = hb * 32 + wn * 16 + (lid & 3) * 2;
        #pragma unroll
        for (int ni = 0; ni < 8; ++ni) {
            const int gate = ni & 3;
            const int h = hq + ((ni >> 2) << 3);
            const float* bp = (gate == 0) ? bi : (gate == 1) ? bf
                            : (gate == 2) ? bo : bg;
            const float b0 = __ldg(&bp[h]);
            const float b1 = __ldg(&bp[h + 1]);
            #pragma unroll
            for (int mi = 0; mi < 2; ++mi) {
                acc[mi][ni][0] = b0; acc[mi][ni][1] = b1;
                acc[mi][ni][2] = b0; acc[mi][ni][3] = b1;
            }
        }
    }

    // ldmatrix lane coordinates
    const int a_r = (lid & 15);
    const int a_c = (lid >> 4);
    const int b_r = ((lid >> 4) << 3) + (lid & 7);
    const int b_c = ((lid >> 3) & 1);

    #pragma unroll 1
    for (int it = 0; it < NITER; ++it) {
        if (it + 1 < NITER) asm volatile("cp.async.wait_group 1;" ::: "memory");
        else                asm volatile("cp.async.wait_group 0;" ::: "memory");
        __syncthreads();

        if (it + 2 < NITER) issue(it + 2);

        const uint32_t smA = sb + (uint32_t)(it % NST) * STAGE_BYTES;
        const uint32_t smB = smA + 16384;

        uint32_t a[2][2][4], b[2][8][2];   // double-buffered fragments
        {
            #pragma unroll
            for (int mi = 0; mi < 2; ++mi)
                ldm_x4(a[0][mi], smA + sw(wm * 32 + mi * 16 + a_r, a_c));
            #pragma unroll
            for (int n2 = 0; n2 < 4; ++n2) {
                uint32_t t4[4];
                ldm_x4(t4, smB + sw(wn * 64 + n2 * 16 + b_r, b_c));
                b[0][n2 * 2][0] = t4[0]; b[0][n2 * 2][1] = t4[1];
                b[0][n2 * 2 + 1][0] = t4[2]; b[0][n2 * 2 + 1][1] = t4[3];
            }
        }
        #pragma unroll
        for (int ks = 0; ks < 4; ++ks) {
            const int cur = ks & 1, nxt = cur ^ 1;
            if (ks < 3) {
                const int kc = (ks + 1) * 2;
                #pragma unroll
                for (int mi = 0; mi < 2; ++mi)
                    ldm_x4(a[nxt][mi], smA + sw(wm * 32 + mi * 16 + a_r, kc + a_c));
                #pragma unroll
                for (int n2 = 0; n2 < 4; ++n2) {
                    uint32_t t4[4];
                    ldm_x4(t4, smB + sw(wn * 64 + n2 * 16 + b_r, kc + b_c));
                    b[nxt][n2 * 2][0] = t4[0]; b[nxt][n2 * 2][1] = t4[1];
                    b[nxt][n2 * 2 + 1][0] = t4[2]; b[nxt][n2 * 2 + 1][1] = t4[3];
                }
            }
            #pragma unroll
            for (int mi = 0; mi < 2; ++mi)
                #pragma unroll
                for (int ni = 0; ni < 8; ++ni)
                    mma16816(acc[mi][ni], a[cur][mi], b[cur][ni]);
        }
    }

    // ---- register-local epilogue (gate quads live in this thread) -----------
    #pragma unroll
    for (int mi = 0; mi < 2; ++mi) {
        const int r_base = mb * 128 + wm * 32 + mi * 16 + (lid >> 2);
        #pragma unroll
        for (int ho = 0; ho < 2; ++ho) {
            const int hg = hb * 32 + wn * 16 + ho * 8 + (lid & 3) * 2;
            #pragma unroll
            for (int pr = 0; pr < 2; ++pr) {       // row +0 / +8
                const int r = r_base + pr * 8;
                const size_t off = (size_t)r * HID + hg;
                const float2 pc = *(const float2*)(prev_c + off);
                const int q0 = pr * 2, q1 = pr * 2 + 1;
                const float i0 = sigmoid_f(acc[mi][ho * 4 + 0][q0]);
                const float f0 = sigmoid_f(acc[mi][ho * 4 + 1][q0]);
                const float o0 = sigmoid_f(acc[mi][ho * 4 + 2][q0]);
                const float g0 = tanh_f   (acc[mi][ho * 4 + 3][q0]);
                const float i1 = sigmoid_f(acc[mi][ho * 4 + 0][q1]);
                const float f1 = sigmoid_f(acc[mi][ho * 4 + 1][q1]);
                const float o1 = sigmoid_f(acc[mi][ho * 4 + 2][q1]);
                const float g1 = tanh_f   (acc[mi][ho * 4 + 3][q1]);
                const float c0 = f0 * pc.x + i0 * g0;
                const float c1 = f1 * pc.y + i1 * g1;
                *(float2*)(h_out + off) = make_float2(tanh_f(c0) * o0,
                                                      tanh_f(c1) * o1);
                *(float2*)(c_out + off) = make_float2(c0, c1);
            }
        }
    }
}

// ---------------------------------------------------------------------------
extern "C" void kernel_launch(void* const* d_in, const int* in_sizes, int n_in,
                              void* d_out, int out_size) {
    const float* input_ = (const float*)d_in[0];
    const float* prev_h = (const float*)d_in[1];
    const float* prev_c = (const float*)d_in[2];
    const float* W_i = (const float*)d_in[3];  const float* b_i = (const float*)d_in[4];
    const float* W_f = (const float*)d_in[5];  const float* b_f = (const float*)d_in[6];
    const float* W_g = (const float*)d_in[7];  const float* b_g = (const float*)d_in[8];
    const float* W_o = (const float*)d_in[9];  const float* b_o = (const float*)d_in[10];

    float* h_out = (float*)d_out;
    float* c_out = h_out + (size_t)BATCH * HID;

    convAW<<<4608, 256>>>(prev_h, input_, W_i, W_f, W_o, W_g);

    cudaFuncSetAttribute(lstm_fp16_gemm,
                         cudaFuncAttributeMaxDynamicSharedMemorySize, DYN_BYTES);
    dim3 grid(16, 128);
    lstm_fp16_gemm<<<grid, 256, DYN_BYTES>>>(prev_c, b_i, b_f, b_o, b_g,
                                             h_out, c_out);
}